// round 3
// baseline (speedup 1.0000x reference)
#include <cuda_runtime.h>
#include <math.h>

#define BB    4
#define SSEQ  4096
#define IND   1024
#define OUTD  1024
#define EE    8
#define LSCALE 512.0f

// ---- scratch (device globals; allocation is forbidden) ----
__device__ float g_seg[BB * IND];               // 16 KB : per-batch column sums of x
__device__ float g_h[(size_t)BB * SSEQ * EE];   // 512 KB: all-expert dots (L2 resident)
__device__ float g_coef[BB * 2];
__device__ int   g_idx[BB * 2];

typedef unsigned long long u64;

__device__ __forceinline__ void fma2(u64& d, u64 a, u64 b) {
    asm("fma.rn.f32x2 %0, %1, %2, %0;" : "+l"(d) : "l"(a), "l"(b));
}
__device__ __forceinline__ u64 dup2(float x) {
    u64 d;
    asm("mov.b64 %0, {%1, %1};" : "=l"(d) : "f"(x));
    return d;
}
__device__ __forceinline__ u64 pack2(float lo, float hi) {
    u64 d;
    asm("mov.b64 %0, {%1, %2};" : "=l"(d) : "f"(lo), "f"(hi));
    return d;
}
__device__ __forceinline__ float lo2(u64 v) { return __uint_as_float((unsigned)(v & 0xffffffffull)); }
__device__ __forceinline__ float hi2(u64 v) { return __uint_as_float((unsigned)(v >> 32)); }

// ------------------------------------------------------------------
// K1: h[b,s,e] = x[b,s,:]·A_e (8 experts) + per-batch column sums.
// 1024 blocks (16 tokens each), 256 thr, 4 CTAs/SM target.
// Lane owns 4 consecutive k per 128-chunk; x via direct LDG.128.
// Experts paired in f32x2: acc[tok][p] = (h_{2p}, h_{2p+1}).
// A pre-packed in shared as u64 (A[2p][k], A[2p+1][k]) -> the hot
// loop has zero packing on the A side, one dup-MOV per x scalar.
// ------------------------------------------------------------------
#define TPW  2      // tokens per warp
#define TOKB 16     // tokens per block (8 warps)

__global__ void __launch_bounds__(256, 4) k1_dots(const float* __restrict__ x,
                                                  const float* __restrict__ lora_A) {
    __shared__ u64   A_p[4 * IND];   // 32 KB : [epair][k] packed (e=2p, e=2p+1)
    __shared__ float seg_s[IND];     //  4 KB : per-block column sums

    const int tid  = threadIdx.x;
    const int w    = tid >> 5;
    const int lane = tid & 31;
    const int b       = blockIdx.x >> 8;            // 256 blocks per batch
    const int tokbase = (blockIdx.x & 255) * TOKB;

    // ---- prologue: pack A into shared, zero seg buffer ----
    #pragma unroll
    for (int j = 0; j < 16; ++j) {
        int idx = tid + j * 256;                    // 0..4095
        int p = idx >> 10, k = idx & 1023;
        A_p[idx] = pack2(lora_A[(2 * p) * IND + k], lora_A[(2 * p + 1) * IND + k]);
    }
    ((float4*)seg_s)[tid] = make_float4(0.f, 0.f, 0.f, 0.f);
    __syncthreads();

    u64 acc[TPW][4];
    #pragma unroll
    for (int i = 0; i < TPW; ++i)
        #pragma unroll
        for (int p = 0; p < 4; ++p) acc[i][p] = 0ull;

    const float* xw = x + ((size_t)(b * SSEQ + tokbase + w * TPW)) * IND;

    #pragma unroll 1
    for (int c = 0; c < 8; ++c) {                   // 8 k-chunks of 128
        const int koff = c * 128 + lane * 4;

        float4 xv0 = *(const float4*)(xw + koff);
        float4 xv1 = *(const float4*)(xw + IND + koff);
        float x0a[4] = {xv0.x, xv0.y, xv0.z, xv0.w};
        float x1a[4] = {xv1.x, xv1.y, xv1.z, xv1.w};

        // segment partial (spread-address shared atomics, ~2cyc/lane)
        atomicAdd(&seg_s[koff + 0], xv0.x + xv1.x);
        atomicAdd(&seg_s[koff + 1], xv0.y + xv1.y);
        atomicAdd(&seg_s[koff + 2], xv0.z + xv1.z);
        atomicAdd(&seg_s[koff + 3], xv0.w + xv1.w);

        const u64* Ab = &A_p[koff];
        #pragma unroll
        for (int kk = 0; kk < 4; ++kk) {
            u64 xd0 = dup2(x0a[kk]);
            u64 xd1 = dup2(x1a[kk]);
            #pragma unroll
            for (int p = 0; p < 4; ++p) {
                u64 a = Ab[p * IND + kk];           // LDS.64, conflict-free
                fma2(acc[0][p], xd0, a);
                fma2(acc[1][p], xd1, a);
            }
        }
    }

    // ---- per-token cross-lane reduction + h store ----
    #pragma unroll
    for (int i = 0; i < TPW; ++i) {
        float v[EE];
        #pragma unroll
        for (int p = 0; p < 4; ++p) { v[2 * p] = lo2(acc[i][p]); v[2 * p + 1] = hi2(acc[i][p]); }
        #pragma unroll
        for (int off = 16; off; off >>= 1)
            #pragma unroll
            for (int e = 0; e < EE; ++e)
                v[e] += __shfl_xor_sync(0xffffffffu, v[e], off);
        if (lane == 0) {
            size_t gt = (size_t)b * SSEQ + tokbase + w * TPW + i;
            *(float4*)&g_h[gt * EE]     = make_float4(v[0], v[1], v[2], v[3]);
            *(float4*)&g_h[gt * EE + 4] = make_float4(v[4], v[5], v[6], v[7]);
        }
    }

    // ---- flush block seg sums to global ----
    __syncthreads();
    {
        float4 s = ((float4*)seg_s)[tid];
        float* dst = &g_seg[b * IND + tid * 4];
        atomicAdd(dst + 0, s.x);
        atomicAdd(dst + 1, s.y);
        atomicAdd(dst + 2, s.z);
        atomicAdd(dst + 3, s.w);
    }
}

// ------------------------------------------------------------------
// K2: logits = seg_mean·G^T + b ; softmax ; top-2 ; coef = 512*w.
// Also re-zeroes g_seg for the next graph replay.
// ------------------------------------------------------------------
__global__ void k2_gate(const float* __restrict__ gate_w,
                        const float* __restrict__ gate_b) {
    __shared__ float dots[BB * EE];
    int tid = threadIdx.x;                  // 1024 threads
    int pair = tid >> 5, lane = tid & 31;   // 32 (b,e) pairs, one warp each
    int b = pair >> 3, e = pair & 7;

    float s = 0.f;
    for (int k = lane * 4; k < IND; k += 128) {
        float4 a = *(const float4*)&g_seg[b * IND + k];
        float4 g = *(const float4*)&gate_w[e * IND + k];
        s += a.x * g.x + a.y * g.y + a.z * g.z + a.w * g.w;
    }
    #pragma unroll
    for (int o = 16; o; o >>= 1) s += __shfl_xor_sync(0xffffffffu, s, o);
    if (lane == 0) dots[pair] = s * (1.0f / (float)SSEQ) + gate_b[e];
    __syncthreads();

    // zero g_seg for next replay (4096 floats = 1024 float4)
    ((float4*)g_seg)[tid] = make_float4(0.f, 0.f, 0.f, 0.f);

    if (tid < BB) {
        int bb = tid;
        float l[EE]; float mx = -1e30f;
        #pragma unroll
        for (int i = 0; i < EE; ++i) { l[i] = dots[bb * EE + i]; mx = fmaxf(mx, l[i]); }
        float sum = 0.f;
        #pragma unroll
        for (int i = 0; i < EE; ++i) { l[i] = expf(l[i] - mx); sum += l[i]; }
        int i0 = 0;
        #pragma unroll
        for (int i = 1; i < EE; ++i) if (l[i] > l[i0]) i0 = i;     // ties -> lowest idx
        int i1 = (i0 == 0) ? 1 : 0;
        #pragma unroll
        for (int i = 0; i < EE; ++i) if (i != i0 && l[i] > l[i1]) i1 = i;
        g_idx[bb * 2] = i0;  g_idx[bb * 2 + 1] = i1;
        float f = LSCALE / sum;
        g_coef[bb * 2]     = l[i0] * f;
        g_coef[bb * 2 + 1] = l[i1] * f;
    }
}

// ------------------------------------------------------------------
// K3: out[b,s,:] = c0*B_{e0} + c1*B_{e1}. 16 tokens/block, 1024
// blocks, unroll-4 (bounded live regs, pipelined STG.128).
// ------------------------------------------------------------------
#define TC 16
__global__ void __launch_bounds__(256) k3_out(const float* __restrict__ lora_B,
                                              float* __restrict__ out) {
    __shared__ float2 cs[TC];
    const int tid = threadIdx.x;
    const int b = blockIdx.x >> 8;                 // 256 blocks per batch
    const int tokbase = (blockIdx.x & 255) * TC;
    const int e0 = g_idx[b * 2], e1 = g_idx[b * 2 + 1];
    const float w0 = g_coef[b * 2], w1 = g_coef[b * 2 + 1];

    if (tid < TC) {
        size_t gt = (size_t)b * SSEQ + tokbase + tid;
        cs[tid] = make_float2(w0 * g_h[gt * EE + e0], w1 * g_h[gt * EE + e1]);
    }
    float4 B0 = *(const float4*)&lora_B[e0 * OUTD + tid * 4];
    float4 B1 = *(const float4*)&lora_B[e1 * OUTD + tid * 4];
    __syncthreads();

    float4* ob = (float4*)out + ((size_t)b * SSEQ + tokbase) * (OUTD / 4) + tid;
    #pragma unroll 4
    for (int i = 0; i < TC; ++i) {
        float2 cc = cs[i];
        float4 v;
        v.x = cc.x * B0.x + cc.y * B1.x;
        v.y = cc.x * B0.y + cc.y * B1.y;
        v.z = cc.x * B0.z + cc.y * B1.z;
        v.w = cc.x * B0.w + cc.y * B1.w;
        ob[(size_t)i * (OUTD / 4)] = v;
    }
}

// ------------------------------------------------------------------
extern "C" void kernel_launch(void* const* d_in, const int* in_sizes, int n_in,
                              void* d_out, int out_size) {
    const float* x      = (const float*)d_in[0];
    const float* lora_A = (const float*)d_in[1];
    const float* lora_B = (const float*)d_in[2];
    const float* gate_w = (const float*)d_in[3];
    const float* gate_b = (const float*)d_in[4];
    float* out = (float*)d_out;

    k1_dots<<<BB * (SSEQ / TOKB), 256>>>(x, lora_A);
    k2_gate<<<1, 1024>>>(gate_w, gate_b);
    k3_out<<<BB * (SSEQ / TC), 256>>>(lora_B, out);
}

// round 4
// speedup vs baseline: 1.1713x; 1.1713x over previous
#include <cuda_runtime.h>
#include <math.h>

#define BB    4
#define SSEQ  4096
#define IND   1024
#define OUTD  1024
#define EE    8
#define LSCALE 512.0f

// ---- scratch (device globals; allocation is forbidden) ----
__device__ float g_seg[BB * IND];               // 16 KB : per-batch column sums of x
__device__ float g_h[(size_t)BB * SSEQ * EE];   // 512 KB: all-expert dots (L2 resident)
__device__ float g_coef[BB * 2];
__device__ int   g_idx[BB * 2];

typedef unsigned long long u64;

__device__ __forceinline__ void fma2(u64& d, u64 a, u64 b) {
    asm("fma.rn.f32x2 %0, %1, %2, %0;" : "+l"(d) : "l"(a), "l"(b));
}
__device__ __forceinline__ float lo2(u64 v) { return __uint_as_float((unsigned)(v & 0xffffffffull)); }
__device__ __forceinline__ float hi2(u64 v) { return __uint_as_float((unsigned)(v >> 32)); }

// ------------------------------------------------------------------
// K1: h[b,s,e] = x[b,s,:]·A_e (8 experts) + per-batch column sums.
// 1024 blocks (16 tokens), 256 thr, 64KB dyn smem -> 3 CTAs/SM.
// Lane owns 4 consecutive k per 128-chunk (chunk order staggered by
// warp). x via direct LDG.128; A staged once as [e][k] floats; math
// is k-paired f32x2 FMAs. Seg sums: one STS.128 per (warp,chunk)
// into a private row -- NO atomics in the hot loop.
// ------------------------------------------------------------------
#define TPW  2      // tokens per warp
#define TOKB 16     // tokens per block (8 warps)

extern __shared__ float s_dyn[];

__global__ void __launch_bounds__(256, 3) k1_dots(const float* __restrict__ x,
                                                  const float* __restrict__ lora_A) {
    float* A_s  = s_dyn;          // 32 KB : [e][1024]
    float* segp = s_dyn + 8192;   // 32 KB : [warp][1024]

    const int tid  = threadIdx.x;
    const int w    = tid >> 5;
    const int lane = tid & 31;
    const int b       = blockIdx.x >> 8;            // 256 blocks per batch
    const int tokbase = (blockIdx.x & 255) * TOKB;

    // stage A once (pure float4 copy, coalesced, conflict-free)
    #pragma unroll
    for (int j = 0; j < 8; ++j) {
        int i4 = tid + j * 256;                     // 2048 float4
        ((float4*)A_s)[i4] = ((const float4*)lora_A)[i4];
    }
    __syncthreads();

    u64 acc[TPW][EE];
    #pragma unroll
    for (int i = 0; i < TPW; ++i)
        #pragma unroll
        for (int e = 0; e < EE; ++e) acc[i][e] = 0ull;

    const float* xw = x + ((size_t)(b * SSEQ + tokbase + w * TPW)) * IND;

    #pragma unroll 1
    for (int c = 0; c < 8; ++c) {                   // 8 k-chunks of 128
        const int cc   = (c + w) & 7;               // warp-staggered chunk order
        const int koff = cc * 128 + lane * 4;

        // x for this warp's 2 tokens (coalesced LDG.128)
        double2 xv0 = *(const double2*)(xw + koff);
        double2 xv1 = *(const double2*)(xw + IND + koff);
        u64 x0lo = __double_as_longlong(xv0.x), x0hi = __double_as_longlong(xv0.y);
        u64 x1lo = __double_as_longlong(xv1.x), x1hi = __double_as_longlong(xv1.y);

        // seg partial: each (warp,chunk,lane) slot written exactly once
        {
            float4 s;
            s.x = lo2(x0lo) + lo2(x1lo);
            s.y = hi2(x0lo) + hi2(x1lo);
            s.z = lo2(x0hi) + lo2(x1hi);
            s.w = hi2(x0hi) + hi2(x1hi);
            *(float4*)&segp[w * IND + koff] = s;
        }

        // 8 experts; A as LDS.128, k-paired packed FMAs
        #pragma unroll
        for (int e = 0; e < EE; ++e) {
            double2 av = *(const double2*)&A_s[e * IND + koff];
            u64 alo = __double_as_longlong(av.x);
            u64 ahi = __double_as_longlong(av.y);
            fma2(acc[0][e], x0lo, alo);
            fma2(acc[0][e], x0hi, ahi);
            fma2(acc[1][e], x1lo, alo);
            fma2(acc[1][e], x1hi, ahi);
        }
    }

    // ---- per-token cross-lane reduction + h store ----
    #pragma unroll
    for (int i = 0; i < TPW; ++i) {
        float v[EE];
        #pragma unroll
        for (int e = 0; e < EE; ++e) v[e] = lo2(acc[i][e]) + hi2(acc[i][e]);
        #pragma unroll
        for (int off = 16; off; off >>= 1)
            #pragma unroll
            for (int e = 0; e < EE; ++e)
                v[e] += __shfl_xor_sync(0xffffffffu, v[e], off);
        if (lane == 0) {
            size_t gt = (size_t)b * SSEQ + tokbase + w * TPW + i;
            *(float4*)&g_h[gt * EE]     = make_float4(v[0], v[1], v[2], v[3]);
            *(float4*)&g_h[gt * EE + 4] = make_float4(v[4], v[5], v[6], v[7]);
        }
    }

    // ---- cross-warp seg reduction + REDG ----
    __syncthreads();
    {
        float4 s = ((float4*)segp)[tid];            // warp 0's row
        #pragma unroll
        for (int ww = 1; ww < 8; ++ww) {
            float4 t = *(float4*)&segp[ww * IND + tid * 4];
            s.x += t.x; s.y += t.y; s.z += t.z; s.w += t.w;
        }
        float* dst = &g_seg[b * IND + tid * 4];
        atomicAdd(dst + 0, s.x);
        atomicAdd(dst + 1, s.y);
        atomicAdd(dst + 2, s.z);
        atomicAdd(dst + 3, s.w);
    }
}

// ------------------------------------------------------------------
// K2: logits = seg_mean·G^T + b ; softmax ; top-2 ; coef = 512*w.
// Also re-zeroes g_seg for the next graph replay.
// ------------------------------------------------------------------
__global__ void k2_gate(const float* __restrict__ gate_w,
                        const float* __restrict__ gate_b) {
    __shared__ float dots[BB * EE];
    int tid = threadIdx.x;                  // 1024 threads
    int pair = tid >> 5, lane = tid & 31;   // 32 (b,e) pairs, one warp each
    int b = pair >> 3, e = pair & 7;

    float s = 0.f;
    for (int k = lane * 4; k < IND; k += 128) {
        float4 a = *(const float4*)&g_seg[b * IND + k];
        float4 g = *(const float4*)&gate_w[e * IND + k];
        s += a.x * g.x + a.y * g.y + a.z * g.z + a.w * g.w;
    }
    #pragma unroll
    for (int o = 16; o; o >>= 1) s += __shfl_xor_sync(0xffffffffu, s, o);
    if (lane == 0) dots[pair] = s * (1.0f / (float)SSEQ) + gate_b[e];
    __syncthreads();

    // zero g_seg for next replay (4096 floats = 1024 float4)
    ((float4*)g_seg)[tid] = make_float4(0.f, 0.f, 0.f, 0.f);

    if (tid < BB) {
        int bb = tid;
        float l[EE]; float mx = -1e30f;
        #pragma unroll
        for (int i = 0; i < EE; ++i) { l[i] = dots[bb * EE + i]; mx = fmaxf(mx, l[i]); }
        float sum = 0.f;
        #pragma unroll
        for (int i = 0; i < EE; ++i) { l[i] = expf(l[i] - mx); sum += l[i]; }
        int i0 = 0;
        #pragma unroll
        for (int i = 1; i < EE; ++i) if (l[i] > l[i0]) i0 = i;     // ties -> lowest idx
        int i1 = (i0 == 0) ? 1 : 0;
        #pragma unroll
        for (int i = 0; i < EE; ++i) if (i != i0 && l[i] > l[i1]) i1 = i;
        g_idx[bb * 2] = i0;  g_idx[bb * 2 + 1] = i1;
        float f = LSCALE / sum;
        g_coef[bb * 2]     = l[i0] * f;
        g_coef[bb * 2 + 1] = l[i1] * f;
    }
}

// ------------------------------------------------------------------
// K3: out[b,s,:] = c0*B_{e0} + c1*B_{e1}. 8 tokens/block, 2048
// blocks -> full CTA residency, pipelined STG.128.
// ------------------------------------------------------------------
#define TC 8
__global__ void __launch_bounds__(256) k3_out(const float* __restrict__ lora_B,
                                              float* __restrict__ out) {
    __shared__ float2 cs[TC];
    const int tid = threadIdx.x;
    const int b = blockIdx.x >> 9;                 // 512 blocks per batch
    const int tokbase = (blockIdx.x & 511) * TC;
    const int e0 = g_idx[b * 2], e1 = g_idx[b * 2 + 1];
    const float w0 = g_coef[b * 2], w1 = g_coef[b * 2 + 1];

    if (tid < TC) {
        size_t gt = (size_t)b * SSEQ + tokbase + tid;
        cs[tid] = make_float2(w0 * g_h[gt * EE + e0], w1 * g_h[gt * EE + e1]);
    }
    float4 B0 = *(const float4*)&lora_B[e0 * OUTD + tid * 4];
    float4 B1 = *(const float4*)&lora_B[e1 * OUTD + tid * 4];
    __syncthreads();

    float4* ob = (float4*)out + ((size_t)b * SSEQ + tokbase) * (OUTD / 4) + tid;
    #pragma unroll
    for (int i = 0; i < TC; ++i) {
        float2 cc = cs[i];
        float4 v;
        v.x = cc.x * B0.x + cc.y * B1.x;
        v.y = cc.x * B0.y + cc.y * B1.y;
        v.z = cc.x * B0.z + cc.y * B1.z;
        v.w = cc.x * B0.w + cc.y * B1.w;
        ob[(size_t)i * (OUTD / 4)] = v;
    }
}

// ------------------------------------------------------------------
extern "C" void kernel_launch(void* const* d_in, const int* in_sizes, int n_in,
                              void* d_out, int out_size) {
    const float* x      = (const float*)d_in[0];
    const float* lora_A = (const float*)d_in[1];
    const float* lora_B = (const float*)d_in[2];
    const float* gate_w = (const float*)d_in[3];
    const float* gate_b = (const float*)d_in[4];
    float* out = (float*)d_out;

    static bool attr_set = false;
    if (!attr_set) {
        cudaFuncSetAttribute(k1_dots, cudaFuncAttributeMaxDynamicSharedMemorySize, 65536);
        attr_set = true;
    }

    k1_dots<<<BB * (SSEQ / TOKB), 256, 65536>>>(x, lora_A);
    k2_gate<<<1, 1024>>>(gate_w, gate_b);
    k3_out<<<BB * (SSEQ / TC), 256>>>(lora_B, out);
}

// round 5
// speedup vs baseline: 1.2051x; 1.0288x over previous
#include <cuda_runtime.h>
#include <math.h>

#define BB    4
#define SSEQ  4096
#define IND   1024
#define OUTD  1024
#define EE    8
#define LSCALE 512.0f

// ---- scratch (device globals; allocation is forbidden) ----
__device__ float g_seg[BB * IND];               // 16 KB : per-batch column sums of x
__device__ float g_h[(size_t)BB * SSEQ * EE];   // 512 KB: all-expert dots (L2 resident)
__device__ float g_coef[BB * 2];
__device__ int   g_idx[BB * 2];

typedef unsigned long long u64;

__device__ __forceinline__ void fma2(u64& d, u64 a, u64 b) {
    asm("fma.rn.f32x2 %0, %1, %2, %0;" : "+l"(d) : "l"(a), "l"(b));
}
__device__ __forceinline__ float lo2(u64 v) { return __uint_as_float((unsigned)(v & 0xffffffffull)); }
__device__ __forceinline__ float hi2(u64 v) { return __uint_as_float((unsigned)(v >> 32)); }

// ------------------------------------------------------------------
// K1: h[b,s,e] = x[b,s,:]·A_e (8 experts) + per-batch column sums.
// 1024 blocks (16 tokens), 256 thr, 64KB dyn smem -> 3 CTAs/SM.
// Chunk loop UNROLL 4: 8 LDG.128 in flight per warp (x2 tokens) so
// per-SM MLP ~192 hides DRAM latency. k-paired f32x2 math; A staged
// once; seg sums via write-once per-warp shared rows (no atomics).
// ------------------------------------------------------------------
#define TPW  2      // tokens per warp
#define TOKB 16     // tokens per block (8 warps)

extern __shared__ float s_dyn[];

__global__ void __launch_bounds__(256, 3) k1_dots(const float* __restrict__ x,
                                                  const float* __restrict__ lora_A) {
    float* A_s  = s_dyn;          // 32 KB : [e][1024]
    float* segp = s_dyn + 8192;   // 32 KB : [warp][1024]

    const int tid  = threadIdx.x;
    const int w    = tid >> 5;
    const int lane = tid & 31;
    const int b       = blockIdx.x >> 8;            // 256 blocks per batch
    const int tokbase = (blockIdx.x & 255) * TOKB;

    // stage A once (pure float4 copy, coalesced, conflict-free)
    #pragma unroll
    for (int j = 0; j < 8; ++j) {
        int i4 = tid + j * 256;                     // 2048 float4
        ((float4*)A_s)[i4] = ((const float4*)lora_A)[i4];
    }
    __syncthreads();

    u64 acc[TPW][EE];
    #pragma unroll
    for (int i = 0; i < TPW; ++i)
        #pragma unroll
        for (int e = 0; e < EE; ++e) acc[i][e] = 0ull;

    const float* xw = x + ((size_t)(b * SSEQ + tokbase + w * TPW)) * IND;

    #pragma unroll 4
    for (int c = 0; c < 8; ++c) {                   // 8 k-chunks of 128
        const int cc   = (c + w) & 7;               // warp-staggered chunk order
        const int koff = cc * 128 + lane * 4;

        // x for this warp's 2 tokens (coalesced LDG.128)
        double2 xv0 = *(const double2*)(xw + koff);
        double2 xv1 = *(const double2*)(xw + IND + koff);
        u64 x0lo = __double_as_longlong(xv0.x), x0hi = __double_as_longlong(xv0.y);
        u64 x1lo = __double_as_longlong(xv1.x), x1hi = __double_as_longlong(xv1.y);

        // seg partial: each (warp,chunk,lane) slot written exactly once
        {
            float4 s;
            s.x = lo2(x0lo) + lo2(x1lo);
            s.y = hi2(x0lo) + hi2(x1lo);
            s.z = lo2(x0hi) + lo2(x1hi);
            s.w = hi2(x0hi) + hi2(x1hi);
            *(float4*)&segp[w * IND + koff] = s;
        }

        // 8 experts; A as LDS.128, k-paired packed FMAs
        #pragma unroll
        for (int e = 0; e < EE; ++e) {
            double2 av = *(const double2*)&A_s[e * IND + koff];
            u64 alo = __double_as_longlong(av.x);
            u64 ahi = __double_as_longlong(av.y);
            fma2(acc[0][e], x0lo, alo);
            fma2(acc[0][e], x0hi, ahi);
            fma2(acc[1][e], x1lo, alo);
            fma2(acc[1][e], x1hi, ahi);
        }
    }

    // ---- per-token cross-lane reduction + h store ----
    #pragma unroll
    for (int i = 0; i < TPW; ++i) {
        float v[EE];
        #pragma unroll
        for (int e = 0; e < EE; ++e) v[e] = lo2(acc[i][e]) + hi2(acc[i][e]);
        #pragma unroll
        for (int off = 16; off; off >>= 1)
            #pragma unroll
            for (int e = 0; e < EE; ++e)
                v[e] += __shfl_xor_sync(0xffffffffu, v[e], off);
        if (lane == 0) {
            size_t gt = (size_t)b * SSEQ + tokbase + w * TPW + i;
            *(float4*)&g_h[gt * EE]     = make_float4(v[0], v[1], v[2], v[3]);
            *(float4*)&g_h[gt * EE + 4] = make_float4(v[4], v[5], v[6], v[7]);
        }
    }

    // ---- cross-warp seg reduction + REDG ----
    __syncthreads();
    {
        float4 s = ((float4*)segp)[tid];            // warp 0's row
        #pragma unroll
        for (int ww = 1; ww < 8; ++ww) {
            float4 t = *(float4*)&segp[ww * IND + tid * 4];
            s.x += t.x; s.y += t.y; s.z += t.z; s.w += t.w;
        }
        float* dst = &g_seg[b * IND + tid * 4];
        atomicAdd(dst + 0, s.x);
        atomicAdd(dst + 1, s.y);
        atomicAdd(dst + 2, s.z);
        atomicAdd(dst + 3, s.w);
    }
}

// ------------------------------------------------------------------
// K2: logits = seg_mean·G^T + b ; softmax ; top-2 ; coef = 512*w.
// Also re-zeroes g_seg for the next graph replay.
// ------------------------------------------------------------------
__global__ void k2_gate(const float* __restrict__ gate_w,
                        const float* __restrict__ gate_b) {
    __shared__ float dots[BB * EE];
    int tid = threadIdx.x;                  // 1024 threads
    int pair = tid >> 5, lane = tid & 31;   // 32 (b,e) pairs, one warp each
    int b = pair >> 3, e = pair & 7;

    float s = 0.f;
    for (int k = lane * 4; k < IND; k += 128) {
        float4 a = *(const float4*)&g_seg[b * IND + k];
        float4 g = *(const float4*)&gate_w[e * IND + k];
        s += a.x * g.x + a.y * g.y + a.z * g.z + a.w * g.w;
    }
    #pragma unroll
    for (int o = 16; o; o >>= 1) s += __shfl_xor_sync(0xffffffffu, s, o);
    if (lane == 0) dots[pair] = s * (1.0f / (float)SSEQ) + gate_b[e];
    __syncthreads();

    // zero g_seg for next replay (4096 floats = 1024 float4)
    ((float4*)g_seg)[tid] = make_float4(0.f, 0.f, 0.f, 0.f);

    if (tid < BB) {
        int bb = tid;
        float l[EE]; float mx = -1e30f;
        #pragma unroll
        for (int i = 0; i < EE; ++i) { l[i] = dots[bb * EE + i]; mx = fmaxf(mx, l[i]); }
        float sum = 0.f;
        #pragma unroll
        for (int i = 0; i < EE; ++i) { l[i] = expf(l[i] - mx); sum += l[i]; }
        int i0 = 0;
        #pragma unroll
        for (int i = 1; i < EE; ++i) if (l[i] > l[i0]) i0 = i;     // ties -> lowest idx
        int i1 = (i0 == 0) ? 1 : 0;
        #pragma unroll
        for (int i = 0; i < EE; ++i) if (i != i0 && l[i] > l[i1]) i1 = i;
        g_idx[bb * 2] = i0;  g_idx[bb * 2 + 1] = i1;
        float f = LSCALE / sum;
        g_coef[bb * 2]     = l[i0] * f;
        g_coef[bb * 2 + 1] = l[i1] * f;
    }
}

// ------------------------------------------------------------------
// K3: out[b,s,:] = c0*B_{e0} + c1*B_{e1}. 8 tokens/block, 2048
// blocks -> full CTA residency, pipelined STG.128.
// ------------------------------------------------------------------
#define TC 8
__global__ void __launch_bounds__(256) k3_out(const float* __restrict__ lora_B,
                                              float* __restrict__ out) {
    __shared__ float2 cs[TC];
    const int tid = threadIdx.x;
    const int b = blockIdx.x >> 9;                 // 512 blocks per batch
    const int tokbase = (blockIdx.x & 511) * TC;
    const int e0 = g_idx[b * 2], e1 = g_idx[b * 2 + 1];
    const float w0 = g_coef[b * 2], w1 = g_coef[b * 2 + 1];

    if (tid < TC) {
        size_t gt = (size_t)b * SSEQ + tokbase + tid;
        cs[tid] = make_float2(w0 * g_h[gt * EE + e0], w1 * g_h[gt * EE + e1]);
    }
    float4 B0 = *(const float4*)&lora_B[e0 * OUTD + tid * 4];
    float4 B1 = *(const float4*)&lora_B[e1 * OUTD + tid * 4];
    __syncthreads();

    float4* ob = (float4*)out + ((size_t)b * SSEQ + tokbase) * (OUTD / 4) + tid;
    #pragma unroll
    for (int i = 0; i < TC; ++i) {
        float2 cc = cs[i];
        float4 v;
        v.x = cc.x * B0.x + cc.y * B1.x;
        v.y = cc.x * B0.y + cc.y * B1.y;
        v.z = cc.x * B0.z + cc.y * B1.z;
        v.w = cc.x * B0.w + cc.y * B1.w;
        ob[(size_t)i * (OUTD / 4)] = v;
    }
}

// ------------------------------------------------------------------
extern "C" void kernel_launch(void* const* d_in, const int* in_sizes, int n_in,
                              void* d_out, int out_size) {
    const float* x      = (const float*)d_in[0];
    const float* lora_A = (const float*)d_in[1];
    const float* lora_B = (const float*)d_in[2];
    const float* gate_w = (const float*)d_in[3];
    const float* gate_b = (const float*)d_in[4];
    float* out = (float*)d_out;

    static bool attr_set = false;
    if (!attr_set) {
        cudaFuncSetAttribute(k1_dots, cudaFuncAttributeMaxDynamicSharedMemorySize, 65536);
        attr_set = true;
    }

    k1_dots<<<BB * (SSEQ / TOKB), 256, 65536>>>(x, lora_A);
    k2_gate<<<1, 1024>>>(gate_w, gate_b);
    k3_out<<<BB * (SSEQ / TC), 256>>>(lora_B, out);
}

// round 6
// speedup vs baseline: 1.4462x; 1.2000x over previous
#include <cuda_runtime.h>
#include <math.h>

#define BB    4
#define SSEQ  4096
#define IND   1024
#define OUTD  1024
#define EE    8
#define LSCALE 512.0f

// ---- scratch (device globals; allocation is forbidden) ----
__device__ float g_seg[BB * IND];               // 16 KB : per-batch column sums of x
__device__ float g_h[(size_t)BB * SSEQ * EE];   // 512 KB: all-expert dots (L2 resident)
__device__ float g_coef[BB * 2];
__device__ int   g_idx[BB * 2];

typedef unsigned long long u64;

__device__ __forceinline__ void fma2(u64& d, u64 a, u64 b) {
    asm("fma.rn.f32x2 %0, %1, %2, %0;" : "+l"(d) : "l"(a), "l"(b));
}
__device__ __forceinline__ u64 dup2(float x) {
    u64 d; asm("mov.b64 %0, {%1, %1};" : "=l"(d) : "f"(x)); return d;
}
__device__ __forceinline__ u64 pack2(float lo, float hi) {
    u64 d; asm("mov.b64 %0, {%1, %2};" : "=l"(d) : "f"(lo), "f"(hi)); return d;
}
__device__ __forceinline__ float lo2(u64 v) { return __uint_as_float((unsigned)(v & 0xffffffffull)); }
__device__ __forceinline__ float hi2(u64 v) { return __uint_as_float((unsigned)(v >> 32)); }

// ------------------------------------------------------------------
// K1: h[b,s,e] = x[b,s,:]·A_e (8 experts) + per-batch column sums.
// Round-2 dataflow (TPW=4, TOKB=32, grid=512) + expert-paired f32x2
// accumulators (32 regs instead of 64) -> 3 CTAs/SM instead of 2.
// A pre-packed once in shared as u64 (A[2p][k], A[2p+1][k]).
// Seg sums: write-once per-warp shared rows, no hot-loop atomics.
// ------------------------------------------------------------------
#define TPW  4      // tokens per warp
#define TOKB 32     // tokens per block (8 warps)

extern __shared__ float s_dyn[];

__global__ void __launch_bounds__(256, 3) k1_dots(const float* __restrict__ x,
                                                  const float* __restrict__ lora_A) {
    u64*   A_p  = (u64*)s_dyn;        // 32 KB : [epair p][k] packed (e=2p, 2p+1)
    float* segp = s_dyn + 8192;       // 32 KB : [warp][1024]

    const int tid  = threadIdx.x;
    const int w    = tid >> 5;
    const int lane = tid & 31;
    const int b       = blockIdx.x >> 7;            // 128 blocks per batch
    const int tokbase = (blockIdx.x & 127) * TOKB;

    // ---- prologue: pack A into shared ----
    #pragma unroll
    for (int j = 0; j < 16; ++j) {
        int idx = tid + j * 256;                    // idx = p*1024 + k
        int p = idx >> 10, k = idx & 1023;
        A_p[idx] = pack2(lora_A[(2 * p) * IND + k], lora_A[(2 * p + 1) * IND + k]);
    }
    __syncthreads();

    u64 acc[TPW][4];
    #pragma unroll
    for (int i = 0; i < TPW; ++i)
        #pragma unroll
        for (int p = 0; p < 4; ++p) acc[i][p] = 0ull;

    const float* xw = x + ((size_t)(b * SSEQ + tokbase + w * TPW)) * IND;

    #pragma unroll 2
    for (int c = 0; c < 8; ++c) {                   // 8 k-chunks of 128
        const int cc   = (c + w) & 7;               // warp-staggered chunk order
        const int koff = cc * 128 + lane * 4;

        // x for this warp's 4 tokens (coalesced LDG.128)
        double2 xv[TPW];
        #pragma unroll
        for (int t = 0; t < TPW; ++t)
            xv[t] = *(const double2*)(xw + (size_t)t * IND + koff);

        // seg partial: each (warp,chunk,lane) slot written exactly once
        {
            float4 s = make_float4(0.f, 0.f, 0.f, 0.f);
            #pragma unroll
            for (int t = 0; t < TPW; ++t) {
                u64 xl = __double_as_longlong(xv[t].x);
                u64 xh = __double_as_longlong(xv[t].y);
                s.x += lo2(xl); s.y += hi2(xl);
                s.z += lo2(xh); s.w += hi2(xh);
            }
            *(float4*)&segp[w * IND + koff] = s;
        }

        // 4 k's; per k-pair: dup x scalars, LDS.128 epair A, 32 FMA2
        #pragma unroll
        for (int kk2 = 0; kk2 < 2; ++kk2) {
            u64 xd0[TPW], xd1[TPW];
            #pragma unroll
            for (int t = 0; t < TPW; ++t) {
                u64 xp = __double_as_longlong(kk2 ? xv[t].y : xv[t].x);
                xd0[t] = dup2(lo2(xp));
                xd1[t] = dup2(hi2(xp));
            }
            #pragma unroll
            for (int p = 0; p < 4; ++p) {
                ulonglong2 av = *(const ulonglong2*)&A_p[p * IND + koff + 2 * kk2];
                #pragma unroll
                for (int t = 0; t < TPW; ++t) {
                    fma2(acc[t][p], xd0[t], av.x);
                    fma2(acc[t][p], xd1[t], av.y);
                }
            }
        }
    }

    // ---- per-token cross-lane reduction + h store ----
    #pragma unroll
    for (int i = 0; i < TPW; ++i) {
        float v[EE];
        #pragma unroll
        for (int p = 0; p < 4; ++p) { v[2 * p] = lo2(acc[i][p]); v[2 * p + 1] = hi2(acc[i][p]); }
        #pragma unroll
        for (int off = 16; off; off >>= 1)
            #pragma unroll
            for (int e = 0; e < EE; ++e)
                v[e] += __shfl_xor_sync(0xffffffffu, v[e], off);
        if (lane == 0) {
            size_t gt = (size_t)b * SSEQ + tokbase + w * TPW + i;
            *(float4*)&g_h[gt * EE]     = make_float4(v[0], v[1], v[2], v[3]);
            *(float4*)&g_h[gt * EE + 4] = make_float4(v[4], v[5], v[6], v[7]);
        }
    }

    // ---- cross-warp seg reduction + REDG ----
    __syncthreads();
    {
        float4 s = ((float4*)segp)[tid];            // warp 0's row
        #pragma unroll
        for (int ww = 1; ww < 8; ++ww) {
            float4 t = *(float4*)&segp[ww * IND + tid * 4];
            s.x += t.x; s.y += t.y; s.z += t.z; s.w += t.w;
        }
        float* dst = &g_seg[b * IND + tid * 4];
        atomicAdd(dst + 0, s.x);
        atomicAdd(dst + 1, s.y);
        atomicAdd(dst + 2, s.z);
        atomicAdd(dst + 3, s.w);
    }
}

// ------------------------------------------------------------------
// K2: logits = seg_mean·G^T + b ; softmax ; top-2 ; coef = 512*w.
// Also re-zeroes g_seg for the next graph replay.
// ------------------------------------------------------------------
__global__ void k2_gate(const float* __restrict__ gate_w,
                        const float* __restrict__ gate_b) {
    __shared__ float dots[BB * EE];
    int tid = threadIdx.x;                  // 1024 threads
    int pair = tid >> 5, lane = tid & 31;   // 32 (b,e) pairs, one warp each
    int b = pair >> 3, e = pair & 7;

    float s = 0.f;
    for (int k = lane * 4; k < IND; k += 128) {
        float4 a = *(const float4*)&g_seg[b * IND + k];
        float4 g = *(const float4*)&gate_w[e * IND + k];
        s += a.x * g.x + a.y * g.y + a.z * g.z + a.w * g.w;
    }
    #pragma unroll
    for (int o = 16; o; o >>= 1) s += __shfl_xor_sync(0xffffffffu, s, o);
    if (lane == 0) dots[pair] = s * (1.0f / (float)SSEQ) + gate_b[e];
    __syncthreads();

    // zero g_seg for next replay (4096 floats = 1024 float4)
    ((float4*)g_seg)[tid] = make_float4(0.f, 0.f, 0.f, 0.f);

    if (tid < BB) {
        int bb = tid;
        float l[EE]; float mx = -1e30f;
        #pragma unroll
        for (int i = 0; i < EE; ++i) { l[i] = dots[bb * EE + i]; mx = fmaxf(mx, l[i]); }
        float sum = 0.f;
        #pragma unroll
        for (int i = 0; i < EE; ++i) { l[i] = expf(l[i] - mx); sum += l[i]; }
        int i0 = 0;
        #pragma unroll
        for (int i = 1; i < EE; ++i) if (l[i] > l[i0]) i0 = i;     // ties -> lowest idx
        int i1 = (i0 == 0) ? 1 : 0;
        #pragma unroll
        for (int i = 0; i < EE; ++i) if (i != i0 && l[i] > l[i1]) i1 = i;
        g_idx[bb * 2] = i0;  g_idx[bb * 2 + 1] = i1;
        float f = LSCALE / sum;
        g_coef[bb * 2]     = l[i0] * f;
        g_coef[bb * 2 + 1] = l[i1] * f;
    }
}

// ------------------------------------------------------------------
// K3: out[b,s,:] = c0*B_{e0} + c1*B_{e1}. Warp owns 4 tokens; B rows
// register-resident per lane (strided float4 -> coalesced STG.128);
// coefs via broadcast LDG. No shared, no syncthreads, 32 independent
// stores per thread.
// ------------------------------------------------------------------
#define TC3 32
__global__ void __launch_bounds__(256) k3_out(const float* __restrict__ lora_B,
                                              float* __restrict__ out) {
    const int tid = threadIdx.x;
    const int w = tid >> 5, lane = tid & 31;
    const int b = blockIdx.x >> 7;                 // 128 blocks per batch
    const int tokbase = (blockIdx.x & 127) * TC3;
    const int e0 = g_idx[b * 2], e1 = g_idx[b * 2 + 1];
    const float w0 = g_coef[b * 2], w1 = g_coef[b * 2 + 1];

    float4 B0r[8], B1r[8];
    #pragma unroll
    for (int j = 0; j < 8; ++j) {
        B0r[j] = *(const float4*)&lora_B[e0 * OUTD + j * 128 + lane * 4];
        B1r[j] = *(const float4*)&lora_B[e1 * OUTD + j * 128 + lane * 4];
    }

    #pragma unroll
    for (int t = 0; t < 4; ++t) {
        size_t gt = (size_t)b * SSEQ + tokbase + w * 4 + t;
        float c0 = w0 * __ldg(&g_h[gt * EE + e0]);   // broadcast (same addr per warp)
        float c1 = w1 * __ldg(&g_h[gt * EE + e1]);
        float4* orow = (float4*)out + gt * (OUTD / 4) + lane;
        #pragma unroll
        for (int j = 0; j < 8; ++j) {
            float4 v;
            v.x = c0 * B0r[j].x + c1 * B1r[j].x;
            v.y = c0 * B0r[j].y + c1 * B1r[j].y;
            v.z = c0 * B0r[j].z + c1 * B1r[j].z;
            v.w = c0 * B0r[j].w + c1 * B1r[j].w;
            orow[j * 32] = v;
        }
    }
}

// ------------------------------------------------------------------
extern "C" void kernel_launch(void* const* d_in, const int* in_sizes, int n_in,
                              void* d_out, int out_size) {
    const float* x      = (const float*)d_in[0];
    const float* lora_A = (const float*)d_in[1];
    const float* lora_B = (const float*)d_in[2];
    const float* gate_w = (const float*)d_in[3];
    const float* gate_b = (const float*)d_in[4];
    float* out = (float*)d_out;

    static bool attr_set = false;
    if (!attr_set) {
        cudaFuncSetAttribute(k1_dots, cudaFuncAttributeMaxDynamicSharedMemorySize, 65536);
        attr_set = true;
    }

    k1_dots<<<BB * (SSEQ / TOKB), 256, 65536>>>(x, lora_A);
    k2_gate<<<1, 1024>>>(gate_w, gate_b);
    k3_out<<<BB * (SSEQ / TC3), 256>>>(lora_B, out);
}